// round 14
// baseline (speedup 1.0000x reference)
#include <cuda_runtime.h>
#include <cstdint>

typedef unsigned long long ull;

#define B_   256
#define T_   512
#define IN_  64
#define H_   128
#define G_   512

__device__ float g_xg0[(size_t)T_ * B_ * G_];
__device__ float g_wt0[64 * 512];          // pre-transposed w_ih0: [k][g]

// ---------------- helpers ----------------
__device__ __forceinline__ uint32_t smem_u32(const void* p) {
    uint32_t a;
    asm("{ .reg .u64 t; cvta.to.shared.u64 t, %1; cvt.u32.u64 %0, t; }" : "=r"(a) : "l"(p));
    return a;
}
__device__ __forceinline__ uint32_t mapa_u32(uint32_t addr, uint32_t rank) {
    uint32_t r;
    asm("mapa.shared::cluster.u32 %0, %1, %2;" : "=r"(r) : "r"(addr), "r"(rank));
    return r;
}
__device__ __forceinline__ void stc_v4(uint32_t addr, float4 v) {
    asm volatile("st.shared::cluster.v4.f32 [%0], {%1,%2,%3,%4};"
                 :: "r"(addr), "f"(v.x), "f"(v.y), "f"(v.z), "f"(v.w));
}
#define CLUSTER_ARRIVE() asm volatile("barrier.cluster.arrive.aligned;" ::: "memory")
#define CLUSTER_WAIT()   asm volatile("barrier.cluster.wait.aligned;"   ::: "memory")
#define CLUSTER_SYNC() do { CLUSTER_ARRIVE(); CLUSTER_WAIT(); } while (0)

__device__ __forceinline__ float sigf(float x)  { return 1.0f / (1.0f + __expf(-x)); }
__device__ __forceinline__ float tanh_f(float x){ return 1.0f - 2.0f / (__expf(2.0f * x) + 1.0f); }

__device__ __forceinline__ ull ffma2(ull a, ull b, ull c) {
    ull d; asm("fma.rn.f32x2 %0, %1, %2, %3;" : "=l"(d) : "l"(a), "l"(b), "l"(c)); return d;
}
__device__ __forceinline__ ull add2(ull a, ull b) {
    ull c; asm("add.rn.f32x2 %0, %1, %2;" : "=l"(c) : "l"(a), "l"(b)); return c;
}
__device__ __forceinline__ ull pack2(float x) {
    ull r; asm("mov.b64 %0, {%1, %1};" : "=l"(r) : "f"(x)); return r;
}
__device__ __forceinline__ float2 unpack2(ull v) {
    float2 f; asm("mov.b64 {%0, %1}, %2;" : "=f"(f.x), "=f"(f.y) : "l"(v)); return f;
}

// ---------------- pre-transpose for p1 ----------------
__global__ void pt_kernel(const float* __restrict__ w_ih0) {
    int i = blockIdx.x * 1024 + threadIdx.x;
    int k = i >> 9, g = i & 511;
    g_wt0[i] = w_ih0[g * 64 + k];
}

// ---------------- Phase 1: 8x8 register tiles (1.0 B/MAC) ----------------
#define P1_ROWS    64
#define P1_THREADS 256
#define P1_XT_STRIDE 68
#define P1_WT_OFF   0
#define P1_XT_OFF   (64*512)
#define P1_B_OFF    (P1_XT_OFF + 64*P1_XT_STRIDE)
#define P1_SMEM_FLOATS (P1_B_OFF + 512)

__global__ void __launch_bounds__(P1_THREADS)
p1_kernel(const float* __restrict__ x, const float* __restrict__ b_ih0,
          const float* __restrict__ b_hh0)
{
    extern __shared__ float s1[];
    float* WT   = s1 + P1_WT_OFF;
    float* xT   = s1 + P1_XT_OFF;
    float* bias = s1 + P1_B_OFF;
    const int tid = threadIdx.x;
    const int rowbase = blockIdx.x * P1_ROWS;

    for (int idx = tid; idx < 64 * 512; idx += P1_THREADS) WT[idx] = g_wt0[idx];
    for (int g = tid; g < G_; g += P1_THREADS) bias[g] = b_ih0[g] + b_hh0[g];
    for (int idx = tid; idx < P1_ROWS * IN_ / 4; idx += P1_THREADS) {
        int row = idx >> 4, kq = idx & 15;
        float4 v = reinterpret_cast<const float4*>(x + (size_t)(rowbase + row) * IN_)[kq];
        int k = kq * 4;
        xT[(k + 0) * P1_XT_STRIDE + row] = v.x;
        xT[(k + 1) * P1_XT_STRIDE + row] = v.y;
        xT[(k + 2) * P1_XT_STRIDE + row] = v.z;
        xT[(k + 3) * P1_XT_STRIDE + row] = v.w;
    }
    __syncthreads();

    const int cg  = tid & 63;   // cols 8cg .. 8cg+7 (contiguous)
    const int rgq = tid >> 6;   // 0..3

    for (int it = 0; it < 2; ++it) {
        const int rg = it * 4 + rgq;      // 0..7, rows 8rg..8rg+7
        ull a2[8][4];
        #pragma unroll
        for (int r = 0; r < 8; ++r)
            #pragma unroll
            for (int c = 0; c < 4; ++c) a2[r][c] = 0ull;

        #pragma unroll 2
        for (int k = 0; k < IN_; ++k) {
            const float* xr = xT + k * P1_XT_STRIDE + (rg << 3);
            float4 xv0 = *reinterpret_cast<const float4*>(xr);
            float4 xv1 = *reinterpret_cast<const float4*>(xr + 4);
            const float* wr = WT + (k << 9) + (cg << 3);
            ulonglong2 w0 = *reinterpret_cast<const ulonglong2*>(wr);       // cols 8cg..+3
            ulonglong2 w1 = *reinterpret_cast<const ulonglong2*>(wr + 4);   // cols +4..+7
            ull xd[8] = {pack2(xv0.x), pack2(xv0.y), pack2(xv0.z), pack2(xv0.w),
                         pack2(xv1.x), pack2(xv1.y), pack2(xv1.z), pack2(xv1.w)};
            #pragma unroll
            for (int r = 0; r < 8; ++r) {
                a2[r][0] = ffma2(xd[r], w0.x, a2[r][0]);
                a2[r][1] = ffma2(xd[r], w0.y, a2[r][1]);
                a2[r][2] = ffma2(xd[r], w1.x, a2[r][2]);
                a2[r][3] = ffma2(xd[r], w1.y, a2[r][3]);
            }
        }
        float4 bb0 = *reinterpret_cast<const float4*>(bias + (cg << 3));
        float4 bb1 = *reinterpret_cast<const float4*>(bias + (cg << 3) + 4);
        #pragma unroll
        for (int r = 0; r < 8; ++r) {
            int n = rowbase + (rg << 3) + r;
            int b = n >> 9, t = n & 511;
            float* op = g_xg0 + ((size_t)t * B_ + b) * G_ + (cg << 3);
            float2 p0 = unpack2(a2[r][0]), p1v = unpack2(a2[r][1]);
            float2 p2 = unpack2(a2[r][2]), p3v = unpack2(a2[r][3]);
            *reinterpret_cast<float4*>(op) =
                make_float4(p0.x + bb0.x, p0.y + bb0.y, p1v.x + bb0.z, p1v.y + bb0.w);
            *reinterpret_cast<float4*>(op + 4) =
                make_float4(p2.x + bb1.x, p2.y + bb1.y, p3v.x + bb1.z, p3v.y + bb1.w);
        }
    }
}

// ---------------- Phase 2: R13 champion scan (byte-identical) ----------------
#define SC_THREADS 512
#define CL_N 4
#define BPC  8
#define WS   132
#define HS   12
#define GS   9
#define W0T_OFF 0
#define W1T_OFF (128*WS)                  // 16896
#define H_OFF   (W1T_OFF + 256*WS)        // 50688
#define GT_OFF  (H_OFF + 2*256*HS)        // 56832
#define SC_SMEM_FLOATS (GT_OFF + 128*GS)  // 57984 -> 231936 B

__device__ __forceinline__ void gemm_half(const float* __restrict__ Wb,
                                          const float* __restrict__ hb,
                                          int kc, int rg, int bg, int k0,
                                          ull acc[16])
{
    #pragma unroll
    for (int ii = 0; ii < 8; ++ii) {
        int k = k0 + (ii << 4) + kc;
        const float* wr = Wb + k * WS + (rg << 3);
        ulonglong2 wA = *reinterpret_cast<const ulonglong2*>(wr);       // rows 8rg..+3
        ulonglong2 wB = *reinterpret_cast<const ulonglong2*>(wr + 4);   // rows 8rg+4..+7
        float4 h = *reinterpret_cast<const float4*>(hb + k * HS + (bg << 2));
        ull h0 = pack2(h.x), h1 = pack2(h.y), h2 = pack2(h.z), h3 = pack2(h.w);
        acc[ 0] = ffma2(wA.x, h0, acc[ 0]); acc[ 1] = ffma2(wA.x, h1, acc[ 1]);
        acc[ 2] = ffma2(wA.x, h2, acc[ 2]); acc[ 3] = ffma2(wA.x, h3, acc[ 3]);
        acc[ 4] = ffma2(wA.y, h0, acc[ 4]); acc[ 5] = ffma2(wA.y, h1, acc[ 5]);
        acc[ 6] = ffma2(wA.y, h2, acc[ 6]); acc[ 7] = ffma2(wA.y, h3, acc[ 7]);
        acc[ 8] = ffma2(wB.x, h0, acc[ 8]); acc[ 9] = ffma2(wB.x, h1, acc[ 9]);
        acc[10] = ffma2(wB.x, h2, acc[10]); acc[11] = ffma2(wB.x, h3, acc[11]);
        acc[12] = ffma2(wB.y, h0, acc[12]); acc[13] = ffma2(wB.y, h1, acc[13]);
        acc[14] = ffma2(wB.y, h2, acc[14]); acc[15] = ffma2(wB.y, h3, acc[15]);
    }
}

__device__ __forceinline__ void fold_store(ull F[16], float* __restrict__ gates,
                                           int kc, int rg, int bg)
{
    {   const bool hi = kc & 1;
        #pragma unroll
        for (int i = 0; i < 8; ++i) {
            ull give = hi ? F[i] : F[i + 8];
            ull keep = hi ? F[i + 8] : F[i];
            F[i] = add2(keep, __shfl_xor_sync(0xffffffffu, give, 1));
        } }
    {   const bool hi = kc & 2;
        #pragma unroll
        for (int i = 0; i < 4; ++i) {
            ull give = hi ? F[i] : F[i + 4];
            ull keep = hi ? F[i + 4] : F[i];
            F[i] = add2(keep, __shfl_xor_sync(0xffffffffu, give, 2));
        } }
    {   const bool hi = kc & 4;
        #pragma unroll
        for (int i = 0; i < 2; ++i) {
            ull give = hi ? F[i] : F[i + 2];
            ull keep = hi ? F[i + 2] : F[i];
            F[i] = add2(keep, __shfl_xor_sync(0xffffffffu, give, 4));
        } }
    {   const bool hi = kc & 8;
        ull give = hi ? F[0] : F[1];
        ull keep = hi ? F[1] : F[0];
        F[0] = add2(keep, __shfl_xor_sync(0xffffffffu, give, 8)); }
    const int rp = ((kc & 1) << 1) | ((kc >> 1) & 1);
    const int bb = (((kc >> 2) & 1) << 1) | ((kc >> 3) & 1);
    const int row0 = (rg << 3) + (rp << 1);
    float2 v = unpack2(F[0]);
    gates[row0 * GS + (bg << 2) + bb]       = v.x;
    gates[(row0 + 1) * GS + (bg << 2) + bb] = v.y;
}

__device__ __forceinline__ void push_h(const float* __restrict__ Hb, const uint32_t* hrem,
                                       int irank, int tid, int bufN, int rowbase)
{
    if (tid < 256) {
        const int q  = tid >> 2;           // 0..63: (col, batch-quad)
        const int r4 = tid & 3;
        if (r4 != irank) {
            const int foff = bufN + (rowbase + (q >> 1)) * HS + ((q & 1) << 2);
            float4 v = *reinterpret_cast<const float4*>(Hb + foff);
            stc_v4(hrem[r4] + ((uint32_t)foff << 2), v);
        }
    }
}

__global__ void __launch_bounds__(SC_THREADS, 1) __cluster_dims__(CL_N, 1, 1)
scan_kernel(const float* __restrict__ w_hh0, const float* __restrict__ w_ih1,
            const float* __restrict__ w_hh1, const float* __restrict__ b_ih1,
            const float* __restrict__ b_hh1, const float* __restrict__ fc_w,
            const float* __restrict__ fc_b,  float* __restrict__ out)
{
    extern __shared__ float s2[];
    float* W0T   = s2 + W0T_OFF;
    float* W1T   = s2 + W1T_OFF;   // k 0..127 = w_ih1, 128..255 = w_hh1
    float* Hbuf  = s2 + H_OFF;     // [buf][k 0..255][b] stride HS; k<128 h0 else h1
    float* gates = s2 + GT_OFF;    // [row][b] stride GS

    const int tid = threadIdx.x;
    uint32_t rank;
    asm("mov.u32 %0, %%cluster_ctarank;" : "=r"(rank));
    const int irank = (int)rank;
    const int cbase = (blockIdx.x >> 2) * BPC;

    // ---- prologue: W slices k-major stride WS ----
    for (int idx = tid; idx < 128 * 128; idx += SC_THREADS) {
        int rl = idx >> 7, k = idx & 127;
        int grow = ((rl >> 5) << 7) + irank * 32 + (rl & 31);
        W0T[k * WS + rl]         = w_hh0[grow * H_ + k];
        W1T[k * WS + rl]         = w_ih1[grow * H_ + k];
        W1T[(128 + k) * WS + rl] = w_hh1[grow * H_ + k];
    }
    for (int i = tid; i < 2 * 256 * HS; i += SC_THREADS) Hbuf[i] = 0.0f;

    const uint32_t hloc = smem_u32(Hbuf);
    uint32_t hrem[4];
    #pragma unroll
    for (int r = 0; r < 4; ++r) hrem[r] = mapa_u32(hloc, (uint32_t)r);

    // GEMM mapping
    const int kc = tid & 15;
    const int tl = tid >> 4;
    const int bg = tl & 1;
    const int rg = tl >> 1;
    // elementwise mapping (tid < 256)
    const int eb  = tid >> 5;
    const int ej  = tid & 31;
    const int col = irank * 32 + ej;
    const float* xgbase = g_xg0 + (size_t)(cbase + eb) * G_ + col;

    float bi1i = 0.f, bi1f = 0.f, bi1g = 0.f, bi1o = 0.f;
    if (tid < 256) {
        bi1i = __ldg(b_ih1 + col)       + __ldg(b_hh1 + col);
        bi1f = __ldg(b_ih1 + 128 + col) + __ldg(b_hh1 + 128 + col);
        bi1g = __ldg(b_ih1 + 256 + col) + __ldg(b_hh1 + 256 + col);
        bi1o = __ldg(b_ih1 + 384 + col) + __ldg(b_hh1 + 384 + col);
    }

    CLUSTER_SYNC();

    float c0 = 0.0f, c1 = 0.0f;
    ull acc0[16];

    #pragma unroll
    for (int i = 0; i < 16; ++i) acc0[i] = 0ull;
    gemm_half(W0T, Hbuf, kc, rg, bg, 0, acc0);   // t=0: h0_prev = zeros (buf 0)
    float xg_i = 0.f, xg_f = 0.f, xg_g = 0.f, xg_o = 0.f;
    if (tid < 256) {
        xg_i = __ldg(xgbase);
        xg_f = __ldg(xgbase + 128);
        xg_g = __ldg(xgbase + 256);
        xg_o = __ldg(xgbase + 384);
    }

    for (int t = 0; t < T_; ++t) {
        const int p = t & 1;
        const int bufP = p ? 3072 : 0;        // holds h0_prev / h1_prev
        const int bufN = p ? 0 : 3072;        // receives h0_new / h1_new

        // ---- publish gates0, elementwise layer 0 (LOCAL store) ----
        fold_store(acc0, gates, kc, rg, bg);
        __syncthreads();
        if (tid < 256) {
            float gi = gates[ej * GS + eb]        + xg_i;
            float gf = gates[(32 + ej) * GS + eb] + xg_f;
            float gg = gates[(64 + ej) * GS + eb] + xg_g;
            float go = gates[(96 + ej) * GS + eb] + xg_o;
            float iv = sigf(gi), fv = sigf(gf), gv = tanh_f(gg), ov = sigf(go);
            c0 = fv * c0 + iv * gv;
            float h0 = ov * tanh_f(c0);
            Hbuf[bufN + col * HS + eb] = h0;
        }
        __syncthreads();                           // local h0 visible to pushers
        push_h(Hbuf, hrem, irank, tid, bufN, irank * 32);
        CLUSTER_ARRIVE();                          // W0: h0_new release (192 msgs)

        // ---- GEMM1b (h1_prev) overlaps barrier W0 ----
        ull acc1[16];
        #pragma unroll
        for (int i = 0; i < 16; ++i) acc1[i] = 0ull;
        gemm_half(W1T, Hbuf + bufP, kc, rg, bg, 128, acc1);

        CLUSTER_WAIT();                            // h0_new visible cluster-wide

        // ---- GEMM1a (h0_new) + publish gates1 ----
        gemm_half(W1T, Hbuf + bufN, kc, rg, bg, 0, acc1);
        fold_store(acc1, gates, kc, rg, bg);
        __syncthreads();

        // ---- elementwise layer 1 (LOCAL store) ----
        if (tid < 256) {
            float gi = gates[ej * GS + eb]        + bi1i;
            float gf = gates[(32 + ej) * GS + eb] + bi1f;
            float gg = gates[(64 + ej) * GS + eb] + bi1g;
            float go = gates[(96 + ej) * GS + eb] + bi1o;
            float iv = sigf(gi), fv = sigf(gf), gv = tanh_f(gg), ov = sigf(go);
            c1 = fv * c1 + iv * gv;
            float h1 = ov * tanh_f(c1);
            Hbuf[bufN + (128 + col) * HS + eb] = h1;
        }
        __syncthreads();                           // local h1 visible to pushers
        push_h(Hbuf, hrem, irank, tid, bufN, 128 + irank * 32);
        CLUSTER_ARRIVE();                          // W1: h1_new release

        // ---- next step's GEMM0 + xg prefetch overlap barrier W1 ----
        if (t + 1 < T_) {
            #pragma unroll
            for (int i = 0; i < 16; ++i) acc0[i] = 0ull;
            gemm_half(W0T, Hbuf + bufN, kc, rg, bg, 0, acc0);
            if (tid < 256) {
                const float* xgp = xgbase + (size_t)(t + 1) * (B_ * G_);
                xg_i = __ldg(xgp);
                xg_f = __ldg(xgp + 128);
                xg_g = __ldg(xgp + 256);
                xg_o = __ldg(xgp + 384);
            }
        }
        CLUSTER_WAIT();                            // h1_new visible; full barrier
    }

    // ---- epilogue: out[b] = fc_b + sum_c h1_last[b][c] * fc_w[c] ----
    // t=511: p=1, bufN=0 -> final h1 in buffer 0, rows 128..255
    if (irank == 0 && tid < 256) {
        const int b = tid >> 5;
        const int l = tid & 31;
        float ssum = 0.0f;
        #pragma unroll
        for (int cc = 0; cc < 4; ++cc) {
            int c = l * 4 + cc;
            ssum += Hbuf[(128 + c) * HS + b] * __ldg(fc_w + c);
        }
        #pragma unroll
        for (int d = 16; d > 0; d >>= 1)
            ssum += __shfl_xor_sync(0xffffffffu, ssum, d);
        if (l == 0) out[cbase + b] = ssum + __ldg(fc_b);
    }
    CLUSTER_SYNC();
}

// ---------------------------------------------------------------------------
extern "C" void kernel_launch(void* const* d_in, const int* in_sizes, int n_in,
                              void* d_out, int out_size)
{
    const float* x     = (const float*)d_in[0];
    const float* w_ih0 = (const float*)d_in[1];
    const float* w_hh0 = (const float*)d_in[2];
    const float* b_ih0 = (const float*)d_in[3];
    const float* b_hh0 = (const float*)d_in[4];
    const float* w_ih1 = (const float*)d_in[5];
    const float* w_hh1 = (const float*)d_in[6];
    const float* b_ih1 = (const float*)d_in[7];
    const float* b_hh1 = (const float*)d_in[8];
    const float* fc_w  = (const float*)d_in[9];
    const float* fc_b  = (const float*)d_in[10];
    float* out = (float*)d_out;

    const int p1_smem = P1_SMEM_FLOATS * 4;
    const int sc_smem = SC_SMEM_FLOATS * 4;
    cudaFuncSetAttribute(p1_kernel,   cudaFuncAttributeMaxDynamicSharedMemorySize, p1_smem);
    cudaFuncSetAttribute(scan_kernel, cudaFuncAttributeMaxDynamicSharedMemorySize, sc_smem);

    pt_kernel<<<32, 1024>>>(w_ih0);
    p1_kernel<<<(B_ * T_) / P1_ROWS, P1_THREADS, p1_smem>>>(x, b_ih0, b_hh0);
    scan_kernel<<<(B_ / BPC) * CL_N, SC_THREADS, sc_smem>>>(
        w_hh0, w_ih1, w_hh1, b_ih1, b_hh1, fc_w, fc_b, out);
}

// round 15
// speedup vs baseline: 1.0421x; 1.0421x over previous
#include <cuda_runtime.h>
#include <cstdint>

typedef unsigned long long ull;

#define B_   256
#define T_   512
#define IN_  64
#define H_   128
#define G_   512

__device__ float g_xg0[(size_t)T_ * B_ * G_];
__device__ float g_wt0[64 * 512];          // pre-transposed w_ih0: [k][g]

// ---------------- helpers ----------------
__device__ __forceinline__ uint32_t smem_u32(const void* p) {
    uint32_t a;
    asm("{ .reg .u64 t; cvta.to.shared.u64 t, %1; cvt.u32.u64 %0, t; }" : "=r"(a) : "l"(p));
    return a;
}
__device__ __forceinline__ uint32_t mapa_u32(uint32_t addr, uint32_t rank) {
    uint32_t r;
    asm("mapa.shared::cluster.u32 %0, %1, %2;" : "=r"(r) : "r"(addr), "r"(rank));
    return r;
}
__device__ __forceinline__ void stc_v4(uint32_t addr, float4 v) {
    asm volatile("st.shared::cluster.v4.f32 [%0], {%1,%2,%3,%4};"
                 :: "r"(addr), "f"(v.x), "f"(v.y), "f"(v.z), "f"(v.w));
}
#define CLUSTER_ARRIVE() asm volatile("barrier.cluster.arrive.aligned;" ::: "memory")
#define CLUSTER_WAIT()   asm volatile("barrier.cluster.wait.aligned;"   ::: "memory")
#define CLUSTER_SYNC() do { CLUSTER_ARRIVE(); CLUSTER_WAIT(); } while (0)

__device__ __forceinline__ float sigf(float x)  { return 1.0f / (1.0f + __expf(-x)); }
__device__ __forceinline__ float tanh_f(float x){ return 1.0f - 2.0f / (__expf(2.0f * x) + 1.0f); }

__device__ __forceinline__ ull ffma2(ull a, ull b, ull c) {
    ull d; asm("fma.rn.f32x2 %0, %1, %2, %3;" : "=l"(d) : "l"(a), "l"(b), "l"(c)); return d;
}
__device__ __forceinline__ ull add2(ull a, ull b) {
    ull c; asm("add.rn.f32x2 %0, %1, %2;" : "=l"(c) : "l"(a), "l"(b)); return c;
}
__device__ __forceinline__ ull pack2(float x) {
    ull r; asm("mov.b64 %0, {%1, %1};" : "=l"(r) : "f"(x)); return r;
}
__device__ __forceinline__ float2 unpack2(ull v) {
    float2 f; asm("mov.b64 {%0, %1}, %2;" : "=f"(f.x), "=f"(f.y) : "l"(v)); return f;
}

// ---------------- pre-transpose for p1 ----------------
__global__ void pt_kernel(const float* __restrict__ w_ih0) {
    int i = blockIdx.x * 1024 + threadIdx.x;
    int k = i >> 9, g = i & 511;
    g_wt0[i] = w_ih0[g * 64 + k];
}

// ---------------- Phase 1 (R13 champion form, 4x8 tiles) ----------------
#define P1_ROWS    64
#define P1_THREADS 256
#define P1_XT_STRIDE 68
#define P1_WT_OFF   0
#define P1_XT_OFF   (64*512)
#define P1_B_OFF    (P1_XT_OFF + 64*P1_XT_STRIDE)
#define P1_SMEM_FLOATS (P1_B_OFF + 512)

__global__ void __launch_bounds__(P1_THREADS)
p1_kernel(const float* __restrict__ x, const float* __restrict__ b_ih0,
          const float* __restrict__ b_hh0)
{
    extern __shared__ float s1[];
    float* WT   = s1 + P1_WT_OFF;
    float* xT   = s1 + P1_XT_OFF;
    float* bias = s1 + P1_B_OFF;
    const int tid = threadIdx.x;
    const int rowbase = blockIdx.x * P1_ROWS;

    for (int idx = tid; idx < 64 * 512; idx += P1_THREADS) WT[idx] = g_wt0[idx];
    for (int g = tid; g < G_; g += P1_THREADS) bias[g] = b_ih0[g] + b_hh0[g];
    for (int idx = tid; idx < P1_ROWS * IN_ / 4; idx += P1_THREADS) {
        int row = idx >> 4, kq = idx & 15;
        float4 v = reinterpret_cast<const float4*>(x + (size_t)(rowbase + row) * IN_)[kq];
        int k = kq * 4;
        xT[(k + 0) * P1_XT_STRIDE + row] = v.x;
        xT[(k + 1) * P1_XT_STRIDE + row] = v.y;
        xT[(k + 2) * P1_XT_STRIDE + row] = v.z;
        xT[(k + 3) * P1_XT_STRIDE + row] = v.w;
    }
    __syncthreads();

    const int cg = tid & 63, rgq = tid >> 6;
    for (int it = 0; it < 4; ++it) {
        const int rg = it * 4 + rgq;
        ull a2[4][4];
        #pragma unroll
        for (int r = 0; r < 4; ++r)
            #pragma unroll
            for (int c = 0; c < 4; ++c) a2[r][c] = 0ull;
        #pragma unroll 4
        for (int k = 0; k < IN_; ++k) {
            float4 xv = *reinterpret_cast<const float4*>(xT + k * P1_XT_STRIDE + (rg << 2));
            ulonglong2 w0 = *reinterpret_cast<const ulonglong2*>(WT + (k << 9) + (cg << 2));
            ulonglong2 w1 = *reinterpret_cast<const ulonglong2*>(WT + (k << 9) + 256 + (cg << 2));
            ull xd0 = pack2(xv.x), xd1 = pack2(xv.y), xd2 = pack2(xv.z), xd3 = pack2(xv.w);
            a2[0][0] = ffma2(xd0, w0.x, a2[0][0]); a2[0][1] = ffma2(xd0, w0.y, a2[0][1]);
            a2[0][2] = ffma2(xd0, w1.x, a2[0][2]); a2[0][3] = ffma2(xd0, w1.y, a2[0][3]);
            a2[1][0] = ffma2(xd1, w0.x, a2[1][0]); a2[1][1] = ffma2(xd1, w0.y, a2[1][1]);
            a2[1][2] = ffma2(xd1, w1.x, a2[1][2]); a2[1][3] = ffma2(xd1, w1.y, a2[1][3]);
            a2[2][0] = ffma2(xd2, w0.x, a2[2][0]); a2[2][1] = ffma2(xd2, w0.y, a2[2][1]);
            a2[2][2] = ffma2(xd2, w1.x, a2[2][2]); a2[2][3] = ffma2(xd2, w1.y, a2[2][3]);
            a2[3][0] = ffma2(xd3, w0.x, a2[3][0]); a2[3][1] = ffma2(xd3, w0.y, a2[3][1]);
            a2[3][2] = ffma2(xd3, w1.x, a2[3][2]); a2[3][3] = ffma2(xd3, w1.y, a2[3][3]);
        }
        float4 bb0 = *reinterpret_cast<const float4*>(bias + (cg << 2));
        float4 bb1 = *reinterpret_cast<const float4*>(bias + 256 + (cg << 2));
        #pragma unroll
        for (int r = 0; r < 4; ++r) {
            int n = rowbase + rg * 4 + r;
            int b = n >> 9, t = n & 511;
            float* op = g_xg0 + ((size_t)t * B_ + b) * G_;
            float2 p0 = unpack2(a2[r][0]), p1v = unpack2(a2[r][1]);
            float2 p2 = unpack2(a2[r][2]), p3v = unpack2(a2[r][3]);
            *reinterpret_cast<float4*>(op + (cg << 2)) =
                make_float4(p0.x + bb0.x, p0.y + bb0.y, p1v.x + bb0.z, p1v.y + bb0.w);
            *reinterpret_cast<float4*>(op + 256 + (cg << 2)) =
                make_float4(p2.x + bb1.x, p2.y + bb1.y, p3v.x + bb1.z, p3v.y + bb1.w);
        }
    }
}

// ---------------- Phase 2: single-barrier merged scan + coalesced push ----------------
// 32 clusters x 4 CTAs x 512 threads. Round t (after B(t-1): h0(t), h1(t-1) visible):
//   GEMM1(t) = W_ih1@h0(t) + W_hh1@h1(t-1) -> G1;  GEMM0(t+1) = W_hh0@h0(t) -> G0;
//   sync; merged ew -> h1(t) (LOCAL, bufT rows 128+), h0(t+1) (LOCAL, bufP rows 0-127);
//   sync; push both slices (tid<256: h1; tid>=256: h0; 192 v4 msgs each);
//   ARRIVE; xg prefetch; WAIT == B(t).
// Round-local GEMM reads {bufT r0-127, bufP r128-255} disjoint from writes
// {bufT r128-255, bufP r0-127}; cross-round hazards separated by >=1 barrier.
// W: rotated conflict-free stride 128 (R12-proven).
#define SC_THREADS 512
#define CL_N 4
#define BPC  8
#define HS   12
#define GS   9
#define W0T_OFF 0
#define W1T_OFF 16384
#define H_OFF   49152                 // 2*256*12
#define GT0_OFF 55296
#define GT1_OFF 56448
#define SC_SMEM_FLOATS 57600          // 230400 B

__device__ __forceinline__ void gemm_half(const float* __restrict__ Wb,
                                          const float* __restrict__ hb,
                                          int kc, int rg, int bg, int k0,
                                          ull acc[16])
{
    #pragma unroll
    for (int ii = 0; ii < 8; ++ii) {
        int k = k0 + (ii << 4) + kc;
        const float* wk = Wb + (k << 7);
        int gA = ((rg << 1) + k) & 31;
        int gB = ((rg << 1) + 1 + k) & 31;
        ulonglong2 wA = *reinterpret_cast<const ulonglong2*>(wk + (gA << 2));
        ulonglong2 wB = *reinterpret_cast<const ulonglong2*>(wk + (gB << 2));
        float4 h = *reinterpret_cast<const float4*>(hb + k * HS + (bg << 2));
        ull h0 = pack2(h.x), h1 = pack2(h.y), h2 = pack2(h.z), h3 = pack2(h.w);
        acc[ 0] = ffma2(wA.x, h0, acc[ 0]); acc[ 1] = ffma2(wA.x, h1, acc[ 1]);
        acc[ 2] = ffma2(wA.x, h2, acc[ 2]); acc[ 3] = ffma2(wA.x, h3, acc[ 3]);
        acc[ 4] = ffma2(wA.y, h0, acc[ 4]); acc[ 5] = ffma2(wA.y, h1, acc[ 5]);
        acc[ 6] = ffma2(wA.y, h2, acc[ 6]); acc[ 7] = ffma2(wA.y, h3, acc[ 7]);
        acc[ 8] = ffma2(wB.x, h0, acc[ 8]); acc[ 9] = ffma2(wB.x, h1, acc[ 9]);
        acc[10] = ffma2(wB.x, h2, acc[10]); acc[11] = ffma2(wB.x, h3, acc[11]);
        acc[12] = ffma2(wB.y, h0, acc[12]); acc[13] = ffma2(wB.y, h1, acc[13]);
        acc[14] = ffma2(wB.y, h2, acc[14]); acc[15] = ffma2(wB.y, h3, acc[15]);
    }
}

__device__ __forceinline__ void fold_store(ull F[16], float* __restrict__ gates,
                                           int kc, int rg, int bg)
{
    {   const bool hi = kc & 1;
        #pragma unroll
        for (int i = 0; i < 8; ++i) {
            ull give = hi ? F[i] : F[i + 8];
            ull keep = hi ? F[i + 8] : F[i];
            F[i] = add2(keep, __shfl_xor_sync(0xffffffffu, give, 1));
        } }
    {   const bool hi = kc & 2;
        #pragma unroll
        for (int i = 0; i < 4; ++i) {
            ull give = hi ? F[i] : F[i + 4];
            ull keep = hi ? F[i + 4] : F[i];
            F[i] = add2(keep, __shfl_xor_sync(0xffffffffu, give, 2));
        } }
    {   const bool hi = kc & 4;
        #pragma unroll
        for (int i = 0; i < 2; ++i) {
            ull give = hi ? F[i] : F[i + 2];
            ull keep = hi ? F[i + 2] : F[i];
            F[i] = add2(keep, __shfl_xor_sync(0xffffffffu, give, 4));
        } }
    {   const bool hi = kc & 8;
        ull give = hi ? F[0] : F[1];
        ull keep = hi ? F[1] : F[0];
        F[0] = add2(keep, __shfl_xor_sync(0xffffffffu, give, 8)); }
    const int rp = ((kc & 1) << 1) | ((kc >> 1) & 1);
    const int bb = (((kc >> 2) & 1) << 1) | ((kc >> 3) & 1);
    const int row0 = (rg << 3) + (rp << 1);
    float2 v = unpack2(F[0]);
    gates[row0 * GS + (bg << 2) + bb]       = v.x;
    gates[(row0 + 1) * GS + (bg << 2) + bb] = v.y;
}

// push one 32-col h slice to the 3 peer ranks (64 v4 per rank, 192 msgs).
__device__ __forceinline__ void push_slice(const float* __restrict__ Hb,
                                           const uint32_t* hrem, int irank,
                                           int stid, int buf, int rowbase)
{
    const int q  = stid >> 2;
    const int r4 = stid & 3;
    if (r4 != irank) {
        const int foff = buf + (rowbase + (q >> 1)) * HS + ((q & 1) << 2);
        float4 v = *reinterpret_cast<const float4*>(Hb + foff);
        stc_v4(hrem[r4] + ((uint32_t)foff << 2), v);
    }
}

__global__ void __launch_bounds__(SC_THREADS, 1) __cluster_dims__(CL_N, 1, 1)
scan_kernel(const float* __restrict__ w_hh0, const float* __restrict__ w_ih1,
            const float* __restrict__ w_hh1, const float* __restrict__ b_ih1,
            const float* __restrict__ b_hh1, const float* __restrict__ fc_w,
            const float* __restrict__ fc_b,  float* __restrict__ out)
{
    extern __shared__ float s2[];
    float* W0T  = s2 + W0T_OFF;
    float* W1T  = s2 + W1T_OFF;   // k 0..127 = w_ih1, 128..255 = w_hh1
    float* Hbuf = s2 + H_OFF;     // [buf][k 0..255][b] stride HS
    float* G0   = s2 + GT0_OFF;
    float* G1   = s2 + GT1_OFF;

    const int tid = threadIdx.x;
    uint32_t rank;
    asm("mov.u32 %0, %%cluster_ctarank;" : "=r"(rank));
    const int irank = (int)rank;
    const int cbase = (blockIdx.x >> 2) * BPC;

    // ---- prologue: rotated W slices ----
    for (int idx = tid; idx < 128 * 128; idx += SC_THREADS) {
        int rl = idx >> 7, k = idx & 127;
        int grow = ((rl >> 5) << 7) + irank * 32 + (rl & 31);
        int sa0 = (k << 7) + ((((rl >> 2) + k) & 31) << 2) + (rl & 3);
        int sa1 = ((128 + k) << 7) + ((((rl >> 2) + 128 + k) & 31) << 2) + (rl & 3);
        W0T[sa0] = w_hh0[grow * H_ + k];
        W1T[sa0] = w_ih1[grow * H_ + k];
        W1T[sa1] = w_hh1[grow * H_ + k];
    }
    for (int i = tid; i < 2 * 256 * HS; i += SC_THREADS) Hbuf[i] = 0.0f;

    const uint32_t hloc = smem_u32(Hbuf);
    uint32_t hrem[4];
    #pragma unroll
    for (int r = 0; r < 4; ++r) hrem[r] = mapa_u32(hloc, (uint32_t)r);

    // GEMM mapping
    const int kc = tid & 15;
    const int tl = tid >> 4;
    const int bg = tl & 1;
    const int rg = tl >> 1;        // rows 8rg..8rg+7
    // elementwise mapping (tid < 256)
    const int eb  = tid >> 5;
    const int ej  = tid & 31;
    const int col = irank * 32 + ej;
    const float* xgbase = g_xg0 + (size_t)(cbase + eb) * G_ + col;
    const int stid = tid & 255;

    float bi1i = 0.f, bi1f = 0.f, bi1g = 0.f, bi1o = 0.f;
    if (tid < 256) {
        bi1i = __ldg(b_ih1 + col)       + __ldg(b_hh1 + col);
        bi1f = __ldg(b_ih1 + 128 + col) + __ldg(b_hh1 + 128 + col);
        bi1g = __ldg(b_ih1 + 256 + col) + __ldg(b_hh1 + 256 + col);
        bi1o = __ldg(b_ih1 + 384 + col) + __ldg(b_hh1 + 384 + col);
    }

    CLUSTER_SYNC();   // zeros visible cluster-wide

    float c0 = 0.0f, c1 = 0.0f;
    float xg_i = 0.f, xg_f = 0.f, xg_g = 0.f, xg_o = 0.f;

    // ---- pre-loop: h0(0) = ew(xg(0), c0=0) -> buf0 rows 0..127 ----
    if (tid < 256) {
        float i0 = __ldg(xgbase);
        float g0 = __ldg(xgbase + 256), o0 = __ldg(xgbase + 384);
        float iv = sigf(i0), gv = tanh_f(g0), ov = sigf(o0);
        c0 = iv * gv;
        Hbuf[col * HS + eb] = ov * tanh_f(c0);
        const float* xp = xgbase + (size_t)1 * (B_ * G_);
        xg_i = __ldg(xp); xg_f = __ldg(xp + 128);
        xg_g = __ldg(xp + 256); xg_o = __ldg(xp + 384);
    }
    __syncthreads();
    if (tid < 256) push_slice(Hbuf, hrem, irank, stid, 0, irank * 32);
    CLUSTER_SYNC();   // B(-1): h0(0) visible everywhere

    for (int t = 0; t < T_; ++t) {
        const int bufT = (t & 1) ? 3072 : 0;   // h0(t); receives h1(t)
        const int bufP = (t & 1) ? 0 : 3072;   // h1(t-1); receives h0(t+1)

        // ---- GEMM1(t) ----
        ull acc1[16];
        #pragma unroll
        for (int i = 0; i < 16; ++i) acc1[i] = 0ull;
        gemm_half(W1T, Hbuf + bufT, kc, rg, bg, 0,   acc1);
        gemm_half(W1T, Hbuf + bufP, kc, rg, bg, 128, acc1);
        fold_store(acc1, G1, kc, rg, bg);

        // ---- GEMM0(t+1) ----
        ull acc0[16];
        #pragma unroll
        for (int i = 0; i < 16; ++i) acc0[i] = 0ull;
        gemm_half(W0T, Hbuf + bufT, kc, rg, bg, 0, acc0);
        fold_store(acc0, G0, kc, rg, bg);

        __syncthreads();

        // ---- merged elementwise: h1(t), h0(t+1) (LOCAL stores) ----
        if (tid < 256) {
            float a1i = G1[ej * GS + eb]        + bi1i;
            float a1f = G1[(32 + ej) * GS + eb] + bi1f;
            float a1g = G1[(64 + ej) * GS + eb] + bi1g;
            float a1o = G1[(96 + ej) * GS + eb] + bi1o;
            float a0i = G0[ej * GS + eb]        + xg_i;
            float a0f = G0[(32 + ej) * GS + eb] + xg_f;
            float a0g = G0[(64 + ej) * GS + eb] + xg_g;
            float a0o = G0[(96 + ej) * GS + eb] + xg_o;
            float iv1 = sigf(a1i), fv1 = sigf(a1f), gv1 = tanh_f(a1g), ov1 = sigf(a1o);
            float iv0 = sigf(a0i), fv0 = sigf(a0f), gv0 = tanh_f(a0g), ov0 = sigf(a0o);
            c1 = fv1 * c1 + iv1 * gv1;
            c0 = fv0 * c0 + iv0 * gv0;
            Hbuf[bufT + (128 + col) * HS + eb] = ov1 * tanh_f(c1);
            Hbuf[bufP + col * HS + eb]         = ov0 * tanh_f(c0);
        }
        __syncthreads();                        // local h visible to pushers

        // ---- push both slices concurrently ----
        if (tid < 256) push_slice(Hbuf, hrem, irank, stid, bufT, 128 + irank * 32);
        else           push_slice(Hbuf, hrem, irank, stid, bufP, irank * 32);
        CLUSTER_ARRIVE();                       // B(t) release

        // xg(t+2) prefetch overlaps the barrier
        if (tid < 256) {
            int tn = t + 2; if (tn > 511) tn = 511;
            const float* xp = xgbase + (size_t)tn * (B_ * G_);
            xg_i = __ldg(xp); xg_f = __ldg(xp + 128);
            xg_g = __ldg(xp + 256); xg_o = __ldg(xp + 384);
        }
        CLUSTER_WAIT();                         // h0(t+1), h1(t) visible
    }

    // ---- epilogue: h1(511) in buf1 (t=511 -> bufT=3072), rows 128..255 ----
    if (irank == 0 && tid < 256) {
        const int b = tid >> 5;
        const int l = tid & 31;
        float ssum = 0.0f;
        #pragma unroll
        for (int cc = 0; cc < 4; ++cc) {
            int c = l * 4 + cc;
            ssum += Hbuf[3072 + (128 + c) * HS + b] * __ldg(fc_w + c);
        }
        #pragma unroll
        for (int d = 16; d > 0; d >>= 1)
            ssum += __shfl_xor_sync(0xffffffffu, ssum, d);
        if (l == 0) out[cbase + b] = ssum + __ldg(fc_b);
    }
    CLUSTER_SYNC();
}

// ---------------------------------------------------------------------------
extern "C" void kernel_launch(void* const* d_in, const int* in_sizes, int n_in,
                              void* d_out, int out_size)
{
    const float* x     = (const float*)d_in[0];
    const float* w_ih0 = (const float*)d_in[1];
    const float* w_hh0 = (const float*)d_in[2];
    const float* b_ih0 = (const float*)d_in[3];
    const float* b_hh0 = (const float*)d_in[4];
    const float* w_ih1 = (const float*)d_in[5];
    const float* w_hh1 = (const float*)d_in[6];
    const float* b_ih1 = (const float*)d_in[7];
    const float* b_hh1 = (const float*)d_in[8];
    const float* fc_w  = (const float*)d_in[9];
    const float* fc_b  = (const float*)d_in[10];
    float* out = (float*)d_out;

    const int p1_smem = P1_SMEM_FLOATS * 4;
    const int sc_smem = SC_SMEM_FLOATS * 4;
    cudaFuncSetAttribute(p1_kernel,   cudaFuncAttributeMaxDynamicSharedMemorySize, p1_smem);
    cudaFuncSetAttribute(scan_kernel, cudaFuncAttributeMaxDynamicSharedMemorySize, sc_smem);

    pt_kernel<<<32, 1024>>>(w_ih0);
    p1_kernel<<<(B_ * T_) / P1_ROWS, P1_THREADS, p1_smem>>>(x, b_ih0, b_hh0);
    scan_kernel<<<(B_ / BPC) * CL_N, SC_THREADS, sc_smem>>>(
        w_hh0, w_ih1, w_hh1, b_ih1, b_hh1, fc_w, fc_b, out);
}

// round 16
// speedup vs baseline: 1.0819x; 1.0383x over previous
#include <cuda_runtime.h>
#include <cstdint>

typedef unsigned long long ull;

#define B_   256
#define T_   512
#define IN_  64
#define H_   128
#define G_   512

__device__ float g_xg0[(size_t)T_ * B_ * G_];
__device__ float g_wt0[64 * 512];          // pre-transposed w_ih0: [k][g]

// ---------------- helpers ----------------
__device__ __forceinline__ uint32_t smem_u32(const void* p) {
    uint32_t a;
    asm("{ .reg .u64 t; cvta.to.shared.u64 t, %1; cvt.u32.u64 %0, t; }" : "=r"(a) : "l"(p));
    return a;
}
__device__ __forceinline__ uint32_t mapa_u32(uint32_t addr, uint32_t rank) {
    uint32_t r;
    asm("mapa.shared::cluster.u32 %0, %1, %2;" : "=r"(r) : "r"(addr), "r"(rank));
    return r;
}
__device__ __forceinline__ void stc_v4(uint32_t addr, float4 v) {
    asm volatile("st.shared::cluster.v4.f32 [%0], {%1,%2,%3,%4};"
                 :: "r"(addr), "f"(v.x), "f"(v.y), "f"(v.z), "f"(v.w));
}
#define CLUSTER_ARRIVE() asm volatile("barrier.cluster.arrive.aligned;" ::: "memory")
#define CLUSTER_WAIT()   asm volatile("barrier.cluster.wait.aligned;"   ::: "memory")
#define CLUSTER_SYNC() do { CLUSTER_ARRIVE(); CLUSTER_WAIT(); } while (0)

__device__ __forceinline__ float sigf(float x)  { return 1.0f / (1.0f + __expf(-x)); }
__device__ __forceinline__ float tanh_f(float x){ return 1.0f - 2.0f / (__expf(2.0f * x) + 1.0f); }

__device__ __forceinline__ ull ffma2(ull a, ull b, ull c) {
    ull d; asm("fma.rn.f32x2 %0, %1, %2, %3;" : "=l"(d) : "l"(a), "l"(b), "l"(c)); return d;
}
__device__ __forceinline__ ull add2(ull a, ull b) {
    ull c; asm("add.rn.f32x2 %0, %1, %2;" : "=l"(c) : "l"(a), "l"(b)); return c;
}
__device__ __forceinline__ ull pack2(float x) {
    ull r; asm("mov.b64 %0, {%1, %1};" : "=l"(r) : "f"(x)); return r;
}
__device__ __forceinline__ float2 unpack2(ull v) {
    float2 f; asm("mov.b64 {%0, %1}, %2;" : "=f"(f.x), "=f"(f.y) : "l"(v)); return f;
}

// ---------------- pre-transpose for p1 ----------------
__global__ void pt_kernel(const float* __restrict__ w_ih0) {
    int i = blockIdx.x * 1024 + threadIdx.x;
    int k = i >> 9, g = i & 511;
    g_wt0[i] = w_ih0[g * 64 + k];
}

// ---------------- Phase 1: 128 rows x 512 threads (16 warps/SM) ----------------
#define P1_ROWS    128
#define P1_THREADS 512
#define P1_XT_STRIDE 132
#define P1_WT_OFF   0
#define P1_XT_OFF   (64*512)
#define P1_B_OFF    (P1_XT_OFF + 64*P1_XT_STRIDE)
#define P1_SMEM_FLOATS (P1_B_OFF + 512)    // 41728 -> 166912 B

__global__ void __launch_bounds__(P1_THREADS)
p1_kernel(const float* __restrict__ x, const float* __restrict__ b_ih0,
          const float* __restrict__ b_hh0)
{
    extern __shared__ float s1[];
    float* WT   = s1 + P1_WT_OFF;   // [k][g], stride 512
    float* xT   = s1 + P1_XT_OFF;   // [k][row], stride 132
    float* bias = s1 + P1_B_OFF;
    const int tid = threadIdx.x;
    const int rowbase = blockIdx.x * P1_ROWS;

    for (int idx = tid; idx < 64 * 512; idx += P1_THREADS) WT[idx] = g_wt0[idx];
    for (int g = tid; g < G_; g += P1_THREADS) bias[g] = b_ih0[g] + b_hh0[g];
    for (int idx = tid; idx < P1_ROWS * IN_ / 4; idx += P1_THREADS) {
        int row = idx >> 4, kq = idx & 15;
        float4 v = reinterpret_cast<const float4*>(x + (size_t)(rowbase + row) * IN_)[kq];
        int k = kq * 4;
        xT[(k + 0) * P1_XT_STRIDE + row] = v.x;
        xT[(k + 1) * P1_XT_STRIDE + row] = v.y;
        xT[(k + 2) * P1_XT_STRIDE + row] = v.z;
        xT[(k + 3) * P1_XT_STRIDE + row] = v.w;
    }
    __syncthreads();

    const int cg  = tid & 63;    // col group: cols 4cg..+3 in both halves
    const int rgq = tid >> 6;    // 0..7

    for (int it = 0; it < 4; ++it) {
        const int rg = it * 8 + rgq;       // 0..31, rows 4rg..4rg+3
        ull a2[4][4];
        #pragma unroll
        for (int r = 0; r < 4; ++r)
            #pragma unroll
            for (int c = 0; c < 4; ++c) a2[r][c] = 0ull;
        #pragma unroll 4
        for (int k = 0; k < IN_; ++k) {
            float4 xv = *reinterpret_cast<const float4*>(xT + k * P1_XT_STRIDE + (rg << 2));
            ulonglong2 w0 = *reinterpret_cast<const ulonglong2*>(WT + (k << 9) + (cg << 2));
            ulonglong2 w1 = *reinterpret_cast<const ulonglong2*>(WT + (k << 9) + 256 + (cg << 2));
            ull xd0 = pack2(xv.x), xd1 = pack2(xv.y), xd2 = pack2(xv.z), xd3 = pack2(xv.w);
            a2[0][0] = ffma2(xd0, w0.x, a2[0][0]); a2[0][1] = ffma2(xd0, w0.y, a2[0][1]);
            a2[0][2] = ffma2(xd0, w1.x, a2[0][2]); a2[0][3] = ffma2(xd0, w1.y, a2[0][3]);
            a2[1][0] = ffma2(xd1, w0.x, a2[1][0]); a2[1][1] = ffma2(xd1, w0.y, a2[1][1]);
            a2[1][2] = ffma2(xd1, w1.x, a2[1][2]); a2[1][3] = ffma2(xd1, w1.y, a2[1][3]);
            a2[2][0] = ffma2(xd2, w0.x, a2[2][0]); a2[2][1] = ffma2(xd2, w0.y, a2[2][1]);
            a2[2][2] = ffma2(xd2, w1.x, a2[2][2]); a2[2][3] = ffma2(xd2, w1.y, a2[2][3]);
            a2[3][0] = ffma2(xd3, w0.x, a2[3][0]); a2[3][1] = ffma2(xd3, w0.y, a2[3][1]);
            a2[3][2] = ffma2(xd3, w1.x, a2[3][2]); a2[3][3] = ffma2(xd3, w1.y, a2[3][3]);
        }
        float4 bb0 = *reinterpret_cast<const float4*>(bias + (cg << 2));
        float4 bb1 = *reinterpret_cast<const float4*>(bias + 256 + (cg << 2));
        #pragma unroll
        for (int r = 0; r < 4; ++r) {
            int n = rowbase + rg * 4 + r;
            int b = n >> 9, t = n & 511;
            float* op = g_xg0 + ((size_t)t * B_ + b) * G_;
            float2 p0 = unpack2(a2[r][0]), p1v = unpack2(a2[r][1]);
            float2 p2 = unpack2(a2[r][2]), p3v = unpack2(a2[r][3]);
            *reinterpret_cast<float4*>(op + (cg << 2)) =
                make_float4(p0.x + bb0.x, p0.y + bb0.y, p1v.x + bb0.z, p1v.y + bb0.w);
            *reinterpret_cast<float4*>(op + 256 + (cg << 2)) =
                make_float4(p2.x + bb1.x, p2.y + bb1.y, p3v.x + bb1.z, p3v.y + bb1.w);
        }
    }
}

// ---------------- Phase 2: R15 champion scan (byte-identical) ----------------
#define SC_THREADS 512
#define CL_N 4
#define BPC  8
#define HS   12
#define GS   9
#define W0T_OFF 0
#define W1T_OFF 16384
#define H_OFF   49152                 // 2*256*12
#define GT0_OFF 55296
#define GT1_OFF 56448
#define SC_SMEM_FLOATS 57600          // 230400 B

__device__ __forceinline__ void gemm_half(const float* __restrict__ Wb,
                                          const float* __restrict__ hb,
                                          int kc, int rg, int bg, int k0,
                                          ull acc[16])
{
    #pragma unroll
    for (int ii = 0; ii < 8; ++ii) {
        int k = k0 + (ii << 4) + kc;
        const float* wk = Wb + (k << 7);
        int gA = ((rg << 1) + k) & 31;
        int gB = ((rg << 1) + 1 + k) & 31;
        ulonglong2 wA = *reinterpret_cast<const ulonglong2*>(wk + (gA << 2));
        ulonglong2 wB = *reinterpret_cast<const ulonglong2*>(wk + (gB << 2));
        float4 h = *reinterpret_cast<const float4*>(hb + k * HS + (bg << 2));
        ull h0 = pack2(h.x), h1 = pack2(h.y), h2 = pack2(h.z), h3 = pack2(h.w);
        acc[ 0] = ffma2(wA.x, h0, acc[ 0]); acc[ 1] = ffma2(wA.x, h1, acc[ 1]);
        acc[ 2] = ffma2(wA.x, h2, acc[ 2]); acc[ 3] = ffma2(wA.x, h3, acc[ 3]);
        acc[ 4] = ffma2(wA.y, h0, acc[ 4]); acc[ 5] = ffma2(wA.y, h1, acc[ 5]);
        acc[ 6] = ffma2(wA.y, h2, acc[ 6]); acc[ 7] = ffma2(wA.y, h3, acc[ 7]);
        acc[ 8] = ffma2(wB.x, h0, acc[ 8]); acc[ 9] = ffma2(wB.x, h1, acc[ 9]);
        acc[10] = ffma2(wB.x, h2, acc[10]); acc[11] = ffma2(wB.x, h3, acc[11]);
        acc[12] = ffma2(wB.y, h0, acc[12]); acc[13] = ffma2(wB.y, h1, acc[13]);
        acc[14] = ffma2(wB.y, h2, acc[14]); acc[15] = ffma2(wB.y, h3, acc[15]);
    }
}

__device__ __forceinline__ void fold_store(ull F[16], float* __restrict__ gates,
                                           int kc, int rg, int bg)
{
    {   const bool hi = kc & 1;
        #pragma unroll
        for (int i = 0; i < 8; ++i) {
            ull give = hi ? F[i] : F[i + 8];
            ull keep = hi ? F[i + 8] : F[i];
            F[i] = add2(keep, __shfl_xor_sync(0xffffffffu, give, 1));
        } }
    {   const bool hi = kc & 2;
        #pragma unroll
        for (int i = 0; i < 4; ++i) {
            ull give = hi ? F[i] : F[i + 4];
            ull keep = hi ? F[i + 4] : F[i];
            F[i] = add2(keep, __shfl_xor_sync(0xffffffffu, give, 2));
        } }
    {   const bool hi = kc & 4;
        #pragma unroll
        for (int i = 0; i < 2; ++i) {
            ull give = hi ? F[i] : F[i + 2];
            ull keep = hi ? F[i + 2] : F[i];
            F[i] = add2(keep, __shfl_xor_sync(0xffffffffu, give, 4));
        } }
    {   const bool hi = kc & 8;
        ull give = hi ? F[0] : F[1];
        ull keep = hi ? F[1] : F[0];
        F[0] = add2(keep, __shfl_xor_sync(0xffffffffu, give, 8)); }
    const int rp = ((kc & 1) << 1) | ((kc >> 1) & 1);
    const int bb = (((kc >> 2) & 1) << 1) | ((kc >> 3) & 1);
    const int row0 = (rg << 3) + (rp << 1);
    float2 v = unpack2(F[0]);
    gates[row0 * GS + (bg << 2) + bb]       = v.x;
    gates[(row0 + 1) * GS + (bg << 2) + bb] = v.y;
}

// push one 32-col h slice to the 3 peer ranks (64 v4 per rank, 192 msgs).
__device__ __forceinline__ void push_slice(const float* __restrict__ Hb,
                                           const uint32_t* hrem, int irank,
                                           int stid, int buf, int rowbase)
{
    const int q  = stid >> 2;
    const int r4 = stid & 3;
    if (r4 != irank) {
        const int foff = buf + (rowbase + (q >> 1)) * HS + ((q & 1) << 2);
        float4 v = *reinterpret_cast<const float4*>(Hb + foff);
        stc_v4(hrem[r4] + ((uint32_t)foff << 2), v);
    }
}

__global__ void __launch_bounds__(SC_THREADS, 1) __cluster_dims__(CL_N, 1, 1)
scan_kernel(const float* __restrict__ w_hh0, const float* __restrict__ w_ih1,
            const float* __restrict__ w_hh1, const float* __restrict__ b_ih1,
            const float* __restrict__ b_hh1, const float* __restrict__ fc_w,
            const float* __restrict__ fc_b,  float* __restrict__ out)
{
    extern __shared__ float s2[];
    float* W0T  = s2 + W0T_OFF;
    float* W1T  = s2 + W1T_OFF;   // k 0..127 = w_ih1, 128..255 = w_hh1
    float* Hbuf = s2 + H_OFF;     // [buf][k 0..255][b] stride HS
    float* G0   = s2 + GT0_OFF;
    float* G1   = s2 + GT1_OFF;

    const int tid = threadIdx.x;
    uint32_t rank;
    asm("mov.u32 %0, %%cluster_ctarank;" : "=r"(rank));
    const int irank = (int)rank;
    const int cbase = (blockIdx.x >> 2) * BPC;

    // ---- prologue: rotated W slices ----
    for (int idx = tid; idx < 128 * 128; idx += SC_THREADS) {
        int rl = idx >> 7, k = idx & 127;
        int grow = ((rl >> 5) << 7) + irank * 32 + (rl & 31);
        int sa0 = (k << 7) + ((((rl >> 2) + k) & 31) << 2) + (rl & 3);
        int sa1 = ((128 + k) << 7) + ((((rl >> 2) + 128 + k) & 31) << 2) + (rl & 3);
        W0T[sa0] = w_hh0[grow * H_ + k];
        W1T[sa0] = w_ih1[grow * H_ + k];
        W1T[sa1] = w_hh1[grow * H_ + k];
    }
    for (int i = tid; i < 2 * 256 * HS; i += SC_THREADS) Hbuf[i] = 0.0f;

    const uint32_t hloc = smem_u32(Hbuf);
    uint32_t hrem[4];
    #pragma unroll
    for (int r = 0; r < 4; ++r) hrem[r] = mapa_u32(hloc, (uint32_t)r);

    // GEMM mapping
    const int kc = tid & 15;
    const int tl = tid >> 4;
    const int bg = tl & 1;
    const int rg = tl >> 1;        // rows 8rg..8rg+7
    // elementwise mapping (tid < 256)
    const int eb  = tid >> 5;
    const int ej  = tid & 31;
    const int col = irank * 32 + ej;
    const float* xgbase = g_xg0 + (size_t)(cbase + eb) * G_ + col;
    const int stid = tid & 255;

    float bi1i = 0.f, bi1f = 0.f, bi1g = 0.f, bi1o = 0.f;
    if (tid < 256) {
        bi1i = __ldg(b_ih1 + col)       + __ldg(b_hh1 + col);
        bi1f = __ldg(b_ih1 + 128 + col) + __ldg(b_hh1 + 128 + col);
        bi1g = __ldg(b_ih1 + 256 + col) + __ldg(b_hh1 + 256 + col);
        bi1o = __ldg(b_ih1 + 384 + col) + __ldg(b_hh1 + 384 + col);
    }

    CLUSTER_SYNC();   // zeros visible cluster-wide

    float c0 = 0.0f, c1 = 0.0f;
    float xg_i = 0.f, xg_f = 0.f, xg_g = 0.f, xg_o = 0.f;

    // ---- pre-loop: h0(0) = ew(xg(0), c0=0) -> buf0 rows 0..127 ----
    if (tid < 256) {
        float i0 = __ldg(xgbase);
        float g0 = __ldg(xgbase + 256), o0 = __ldg(xgbase + 384);
        float iv = sigf(i0), gv = tanh_f(g0), ov = sigf(o0);
        c0 = iv * gv;
        Hbuf[col * HS + eb] = ov * tanh_f(c0);
        const float* xp = xgbase + (size_t)1 * (B_ * G_);
        xg_i = __ldg(xp); xg_f = __ldg(xp + 128);
        xg_g = __ldg(xp + 256); xg_o = __ldg(xp + 384);
    }
    __syncthreads();
    if (tid < 256) push_slice(Hbuf, hrem, irank, stid, 0, irank * 32);
    CLUSTER_SYNC();   // B(-1): h0(0) visible everywhere

    for (int t = 0; t < T_; ++t) {
        const int bufT = (t & 1) ? 3072 : 0;   // h0(t); receives h1(t)
        const int bufP = (t & 1) ? 0 : 3072;   // h1(t-1); receives h0(t+1)

        // ---- GEMM1(t) ----
        ull acc1[16];
        #pragma unroll
        for (int i = 0; i < 16; ++i) acc1[i] = 0ull;
        gemm_half(W1T, Hbuf + bufT, kc, rg, bg, 0,   acc1);
        gemm_half(W1T, Hbuf + bufP, kc, rg, bg, 128, acc1);
        fold_store(acc1, G1, kc, rg, bg);

        // ---- GEMM0(t+1) ----
        ull acc0[16];
        #pragma unroll
        for (int i = 0; i < 16; ++i) acc0[i] = 0ull;
        gemm_half(W0T, Hbuf + bufT, kc, rg, bg, 0, acc0);
        fold_store(acc0, G0, kc, rg, bg);

        __syncthreads();

        // ---- merged elementwise: h1(t), h0(t+1) (LOCAL stores) ----
        if (tid < 256) {
            float a1i = G1[ej * GS + eb]        + bi1i;
            float a1f = G1[(32 + ej) * GS + eb] + bi1f;
            float a1g = G1[(64 + ej) * GS + eb] + bi1g;
            float a1o = G1[(96 + ej) * GS + eb] + bi1o;
            float a0i = G0[ej * GS + eb]        + xg_i;
            float a0f = G0[(32 + ej) * GS + eb] + xg_f;
            float a0g = G0[(64 + ej) * GS + eb] + xg_g;
            float a0o = G0[(96 + ej) * GS + eb] + xg_o;
            float iv1 = sigf(a1i), fv1 = sigf(a1f), gv1 = tanh_f(a1g), ov1 = sigf(a1o);
            float iv0 = sigf(a0i), fv0 = sigf(a0f), gv0 = tanh_f(a0g), ov0 = sigf(a0o);
            c1 = fv1 * c1 + iv1 * gv1;
            c0 = fv0 * c0 + iv0 * gv0;
            Hbuf[bufT + (128 + col) * HS + eb] = ov1 * tanh_f(c1);
            Hbuf[bufP + col * HS + eb]         = ov0 * tanh_f(c0);
        }
        __syncthreads();                        // local h visible to pushers

        // ---- push both slices concurrently ----
        if (tid < 256) push_slice(Hbuf, hrem, irank, stid, bufT, 128 + irank * 32);
        else           push_slice(Hbuf, hrem, irank, stid, bufP, irank * 32);
        CLUSTER_ARRIVE();                       // B(t) release

        // xg(t+2) prefetch overlaps the barrier
        if (tid < 256) {
            int tn = t + 2; if (tn > 511) tn = 511;
            const float* xp = xgbase + (size_t)tn * (B_ * G_);
            xg_i = __ldg(xp); xg_f = __ldg(xp + 128);
            xg_g = __ldg(xp + 256); xg_o = __ldg(xp + 384);
        }
        CLUSTER_WAIT();                         // h0(t+1), h1(t) visible
    }

    // ---- epilogue: h1(511) in buf1 (t=511 -> bufT=3072), rows 128..255 ----
    if (irank == 0 && tid < 256) {
        const int b = tid >> 5;
        const int l = tid & 31;
        float ssum = 0.0f;
        #pragma unroll
        for (int cc = 0; cc < 4; ++cc) {
            int c = l * 4 + cc;
            ssum += Hbuf[3072 + (128 + c) * HS + b] * __ldg(fc_w + c);
        }
        #pragma unroll
        for (int d = 16; d > 0; d >>= 1)
            ssum += __shfl_xor_sync(0xffffffffu, ssum, d);
        if (l == 0) out[cbase + b] = ssum + __ldg(fc_b);
    }
    CLUSTER_SYNC();
}

// ---------------------------------------------------------------------------
extern "C" void kernel_launch(void* const* d_in, const int* in_sizes, int n_in,
                              void* d_out, int out_size)
{
    const float* x     = (const float*)d_in[0];
    const float* w_ih0 = (const float*)d_in[1];
    const float* w_hh0 = (const float*)d_in[2];
    const float* b_ih0 = (const float*)d_in[3];
    const float* b_hh0 = (const float*)d_in[4];
    const float* w_ih1 = (const float*)d_in[5];
    const float* w_hh1 = (const float*)d_in[6];
    const float* b_ih1 = (const float*)d_in[7];
    const float* b_hh1 = (const float*)d_in[8];
    const float* fc_w  = (const float*)d_in[9];
    const float* fc_b  = (const float*)d_in[10];
    float* out = (float*)d_out;

    const int p1_smem = P1_SMEM_FLOATS * 4;
    const int sc_smem = SC_SMEM_FLOATS * 4;
    cudaFuncSetAttribute(p1_kernel,   cudaFuncAttributeMaxDynamicSharedMemorySize, p1_smem);
    cudaFuncSetAttribute(scan_kernel, cudaFuncAttributeMaxDynamicSharedMemorySize, sc_smem);

    pt_kernel<<<32, 1024>>>(w_ih0);
    p1_kernel<<<(B_ * T_) / P1_ROWS, P1_THREADS, p1_smem>>>(x, b_ih0, b_hh0);
    scan_kernel<<<(B_ / BPC) * CL_N, SC_THREADS, sc_smem>>>(
        w_hh0, w_ih1, w_hh1, b_ih1, b_hh1, fc_w, fc_b, out);
}

// round 17
// speedup vs baseline: 1.2237x; 1.1310x over previous
#include <cuda_runtime.h>
#include <cstdint>

typedef unsigned long long ull;

#define B_   256
#define T_   512
#define IN_  64
#define H_   128
#define G_   512

__device__ float g_xg0[(size_t)T_ * B_ * G_];
__device__ float g_wt0[64 * 512];          // pre-transposed w_ih0: [k][g]

// ---------------- helpers ----------------
__device__ __forceinline__ uint32_t smem_u32(const void* p) {
    uint32_t a;
    asm("{ .reg .u64 t; cvta.to.shared.u64 t, %1; cvt.u32.u64 %0, t; }" : "=r"(a) : "l"(p));
    return a;
}
__device__ __forceinline__ uint32_t mapa_u32(uint32_t addr, uint32_t rank) {
    uint32_t r;
    asm("mapa.shared::cluster.u32 %0, %1, %2;" : "=r"(r) : "r"(addr), "r"(rank));
    return r;
}
__device__ __forceinline__ void stc_v4(uint32_t addr, float4 v) {
    asm volatile("st.shared::cluster.v4.f32 [%0], {%1,%2,%3,%4};"
                 :: "r"(addr), "f"(v.x), "f"(v.y), "f"(v.z), "f"(v.w));
}
#define CLUSTER_ARRIVE() asm volatile("barrier.cluster.arrive.aligned;" ::: "memory")
#define CLUSTER_WAIT()   asm volatile("barrier.cluster.wait.aligned;"   ::: "memory")
#define CLUSTER_SYNC() do { CLUSTER_ARRIVE(); CLUSTER_WAIT(); } while (0)

__device__ __forceinline__ float sigf(float x)  { return 1.0f / (1.0f + __expf(-x)); }
__device__ __forceinline__ float tanh_f(float x){ return 1.0f - 2.0f / (__expf(2.0f * x) + 1.0f); }

__device__ __forceinline__ ull ffma2(ull a, ull b, ull c) {
    ull d; asm("fma.rn.f32x2 %0, %1, %2, %3;" : "=l"(d) : "l"(a), "l"(b), "l"(c)); return d;
}
__device__ __forceinline__ ull add2(ull a, ull b) {
    ull c; asm("add.rn.f32x2 %0, %1, %2;" : "=l"(c) : "l"(a), "l"(b)); return c;
}
__device__ __forceinline__ ull pack2(float x) {
    ull r; asm("mov.b64 %0, {%1, %1};" : "=l"(r) : "f"(x)); return r;
}
__device__ __forceinline__ float2 unpack2(ull v) {
    float2 f; asm("mov.b64 {%0, %1}, %2;" : "=f"(f.x), "=f"(f.y) : "l"(v)); return f;
}

// ---------------- pre-transpose for p1 ----------------
__global__ void pt_kernel(const float* __restrict__ w_ih0) {
    int i = blockIdx.x * 1024 + threadIdx.x;
    int k = i >> 9, g = i & 511;
    g_wt0[i] = w_ih0[g * 64 + k];
}

// ---------------- Phase 1 (R16 champion: 128 rows x 512 threads) ----------------
#define P1_ROWS    128
#define P1_THREADS 512
#define P1_XT_STRIDE 132
#define P1_WT_OFF   0
#define P1_XT_OFF   (64*512)
#define P1_B_OFF    (P1_XT_OFF + 64*P1_XT_STRIDE)
#define P1_SMEM_FLOATS (P1_B_OFF + 512)

__global__ void __launch_bounds__(P1_THREADS)
p1_kernel(const float* __restrict__ x, const float* __restrict__ b_ih0,
          const float* __restrict__ b_hh0)
{
    extern __shared__ float s1[];
    float* WT   = s1 + P1_WT_OFF;
    float* xT   = s1 + P1_XT_OFF;
    float* bias = s1 + P1_B_OFF;
    const int tid = threadIdx.x;
    const int rowbase = blockIdx.x * P1_ROWS;

    for (int idx = tid; idx < 64 * 512; idx += P1_THREADS) WT[idx] = g_wt0[idx];
    for (int g = tid; g < G_; g += P1_THREADS) bias[g] = b_ih0[g] + b_hh0[g];
    for (int idx = tid; idx < P1_ROWS * IN_ / 4; idx += P1_THREADS) {
        int row = idx >> 4, kq = idx & 15;
        float4 v = reinterpret_cast<const float4*>(x + (size_t)(rowbase + row) * IN_)[kq];
        int k = kq * 4;
        xT[(k + 0) * P1_XT_STRIDE + row] = v.x;
        xT[(k + 1) * P1_XT_STRIDE + row] = v.y;
        xT[(k + 2) * P1_XT_STRIDE + row] = v.z;
        xT[(k + 3) * P1_XT_STRIDE + row] = v.w;
    }
    __syncthreads();

    const int cg  = tid & 63;
    const int rgq = tid >> 6;

    for (int it = 0; it < 4; ++it) {
        const int rg = it * 8 + rgq;
        ull a2[4][4];
        #pragma unroll
        for (int r = 0; r < 4; ++r)
            #pragma unroll
            for (int c = 0; c < 4; ++c) a2[r][c] = 0ull;
        #pragma unroll 4
        for (int k = 0; k < IN_; ++k) {
            float4 xv = *reinterpret_cast<const float4*>(xT + k * P1_XT_STRIDE + (rg << 2));
            ulonglong2 w0 = *reinterpret_cast<const ulonglong2*>(WT + (k << 9) + (cg << 2));
            ulonglong2 w1 = *reinterpret_cast<const ulonglong2*>(WT + (k << 9) + 256 + (cg << 2));
            ull xd0 = pack2(xv.x), xd1 = pack2(xv.y), xd2 = pack2(xv.z), xd3 = pack2(xv.w);
            a2[0][0] = ffma2(xd0, w0.x, a2[0][0]); a2[0][1] = ffma2(xd0, w0.y, a2[0][1]);
            a2[0][2] = ffma2(xd0, w1.x, a2[0][2]); a2[0][3] = ffma2(xd0, w1.y, a2[0][3]);
            a2[1][0] = ffma2(xd1, w0.x, a2[1][0]); a2[1][1] = ffma2(xd1, w0.y, a2[1][1]);
            a2[1][2] = ffma2(xd1, w1.x, a2[1][2]); a2[1][3] = ffma2(xd1, w1.y, a2[1][3]);
            a2[2][0] = ffma2(xd2, w0.x, a2[2][0]); a2[2][1] = ffma2(xd2, w0.y, a2[2][1]);
            a2[2][2] = ffma2(xd2, w1.x, a2[2][2]); a2[2][3] = ffma2(xd2, w1.y, a2[2][3]);
            a2[3][0] = ffma2(xd3, w0.x, a2[3][0]); a2[3][1] = ffma2(xd3, w0.y, a2[3][1]);
            a2[3][2] = ffma2(xd3, w1.x, a2[3][2]); a2[3][3] = ffma2(xd3, w1.y, a2[3][3]);
        }
        float4 bb0 = *reinterpret_cast<const float4*>(bias + (cg << 2));
        float4 bb1 = *reinterpret_cast<const float4*>(bias + 256 + (cg << 2));
        #pragma unroll
        for (int r = 0; r < 4; ++r) {
            int n = rowbase + rg * 4 + r;
            int b = n >> 9, t = n & 511;
            float* op = g_xg0 + ((size_t)t * B_ + b) * G_;
            float2 p0 = unpack2(a2[r][0]), p1v = unpack2(a2[r][1]);
            float2 p2 = unpack2(a2[r][2]), p3v = unpack2(a2[r][3]);
            *reinterpret_cast<float4*>(op + (cg << 2)) =
                make_float4(p0.x + bb0.x, p0.y + bb0.y, p1v.x + bb0.z, p1v.y + bb0.w);
            *reinterpret_cast<float4*>(op + 256 + (cg << 2)) =
                make_float4(p2.x + bb1.x, p2.y + bb1.y, p3v.x + bb1.z, p3v.y + bb1.w);
        }
    }
}

// ---------------- Phase 2: merged-GEMM + split-ew scan ----------------
// R15/R16 single-barrier structure. New: (a) GEMM1a and GEMM0 share h0(t)
// loads in ONE merged loop (72 -> 64 LDS.128/thread/step); (b) elementwise
// split across all 512 threads: tid<256 layer 1 (c1, bias), tid>=256
// layer 0 (c0, xg). Barriers / buffers / push identical to R16.
#define SC_THREADS 512
#define CL_N 4
#define BPC  8
#define HS   12
#define GS   9
#define W0T_OFF 0
#define W1T_OFF 16384
#define H_OFF   49152                 // 2*256*12
#define GT0_OFF 55296
#define GT1_OFF 56448
#define SC_SMEM_FLOATS 57600          // 230400 B

__device__ __forceinline__ void gemm_half(const float* __restrict__ Wb,
                                          const float* __restrict__ hb,
                                          int kc, int rg, int bg, int k0,
                                          ull acc[16])
{
    #pragma unroll
    for (int ii = 0; ii < 8; ++ii) {
        int k = k0 + (ii << 4) + kc;
        const float* wk = Wb + (k << 7);
        int gA = ((rg << 1) + k) & 31;
        int gB = ((rg << 1) + 1 + k) & 31;
        ulonglong2 wA = *reinterpret_cast<const ulonglong2*>(wk + (gA << 2));
        ulonglong2 wB = *reinterpret_cast<const ulonglong2*>(wk + (gB << 2));
        float4 h = *reinterpret_cast<const float4*>(hb + k * HS + (bg << 2));
        ull h0 = pack2(h.x), h1 = pack2(h.y), h2 = pack2(h.z), h3 = pack2(h.w);
        acc[ 0] = ffma2(wA.x, h0, acc[ 0]); acc[ 1] = ffma2(wA.x, h1, acc[ 1]);
        acc[ 2] = ffma2(wA.x, h2, acc[ 2]); acc[ 3] = ffma2(wA.x, h3, acc[ 3]);
        acc[ 4] = ffma2(wA.y, h0, acc[ 4]); acc[ 5] = ffma2(wA.y, h1, acc[ 5]);
        acc[ 6] = ffma2(wA.y, h2, acc[ 6]); acc[ 7] = ffma2(wA.y, h3, acc[ 7]);
        acc[ 8] = ffma2(wB.x, h0, acc[ 8]); acc[ 9] = ffma2(wB.x, h1, acc[ 9]);
        acc[10] = ffma2(wB.x, h2, acc[10]); acc[11] = ffma2(wB.x, h3, acc[11]);
        acc[12] = ffma2(wB.y, h0, acc[12]); acc[13] = ffma2(wB.y, h1, acc[13]);
        acc[14] = ffma2(wB.y, h2, acc[14]); acc[15] = ffma2(wB.y, h3, acc[15]);
    }
}

// merged: acc1 += W1[k 0..127] @ h ; acc0 += W0[k 0..127] @ h (shared h loads)
__device__ __forceinline__ void gemm_dual(const float* __restrict__ W1b,
                                          const float* __restrict__ W0b,
                                          const float* __restrict__ hb,
                                          int kc, int rg, int bg,
                                          ull acc1[16], ull acc0[16])
{
    #pragma unroll
    for (int ii = 0; ii < 8; ++ii) {
        int k = (ii << 4) + kc;
        int gA = ((rg << 1) + k) & 31;
        int gB = ((rg << 1) + 1 + k) & 31;
        const float* wk1 = W1b + (k << 7);
        const float* wk0 = W0b + (k << 7);
        ulonglong2 wA1 = *reinterpret_cast<const ulonglong2*>(wk1 + (gA << 2));
        ulonglong2 wB1 = *reinterpret_cast<const ulonglong2*>(wk1 + (gB << 2));
        ulonglong2 wA0 = *reinterpret_cast<const ulonglong2*>(wk0 + (gA << 2));
        ulonglong2 wB0 = *reinterpret_cast<const ulonglong2*>(wk0 + (gB << 2));
        float4 h = *reinterpret_cast<const float4*>(hb + k * HS + (bg << 2));
        ull h0 = pack2(h.x), h1 = pack2(h.y), h2 = pack2(h.z), h3 = pack2(h.w);
        acc1[ 0] = ffma2(wA1.x, h0, acc1[ 0]); acc1[ 1] = ffma2(wA1.x, h1, acc1[ 1]);
        acc1[ 2] = ffma2(wA1.x, h2, acc1[ 2]); acc1[ 3] = ffma2(wA1.x, h3, acc1[ 3]);
        acc1[ 4] = ffma2(wA1.y, h0, acc1[ 4]); acc1[ 5] = ffma2(wA1.y, h1, acc1[ 5]);
        acc1[ 6] = ffma2(wA1.y, h2, acc1[ 6]); acc1[ 7] = ffma2(wA1.y, h3, acc1[ 7]);
        acc1[ 8] = ffma2(wB1.x, h0, acc1[ 8]); acc1[ 9] = ffma2(wB1.x, h1, acc1[ 9]);
        acc1[10] = ffma2(wB1.x, h2, acc1[10]); acc1[11] = ffma2(wB1.x, h3, acc1[11]);
        acc1[12] = ffma2(wB1.y, h0, acc1[12]); acc1[13] = ffma2(wB1.y, h1, acc1[13]);
        acc1[14] = ffma2(wB1.y, h2, acc1[14]); acc1[15] = ffma2(wB1.y, h3, acc1[15]);
        acc0[ 0] = ffma2(wA0.x, h0, acc0[ 0]); acc0[ 1] = ffma2(wA0.x, h1, acc0[ 1]);
        acc0[ 2] = ffma2(wA0.x, h2, acc0[ 2]); acc0[ 3] = ffma2(wA0.x, h3, acc0[ 3]);
        acc0[ 4] = ffma2(wA0.y, h0, acc0[ 4]); acc0[ 5] = ffma2(wA0.y, h1, acc0[ 5]);
        acc0[ 6] = ffma2(wA0.y, h2, acc0[ 6]); acc0[ 7] = ffma2(wA0.y, h3, acc0[ 7]);
        acc0[ 8] = ffma2(wB0.x, h0, acc0[ 8]); acc0[ 9] = ffma2(wB0.x, h1, acc0[ 9]);
        acc0[10] = ffma2(wB0.x, h2, acc0[10]); acc0[11] = ffma2(wB0.x, h3, acc0[11]);
        acc0[12] = ffma2(wB0.y, h0, acc0[12]); acc0[13] = ffma2(wB0.y, h1, acc0[13]);
        acc0[14] = ffma2(wB0.y, h2, acc0[14]); acc0[15] = ffma2(wB0.y, h3, acc0[15]);
    }
}

__device__ __forceinline__ void fold_store(ull F[16], float* __restrict__ gates,
                                           int kc, int rg, int bg)
{
    {   const bool hi = kc & 1;
        #pragma unroll
        for (int i = 0; i < 8; ++i) {
            ull give = hi ? F[i] : F[i + 8];
            ull keep = hi ? F[i + 8] : F[i];
            F[i] = add2(keep, __shfl_xor_sync(0xffffffffu, give, 1));
        } }
    {   const bool hi = kc & 2;
        #pragma unroll
        for (int i = 0; i < 4; ++i) {
            ull give = hi ? F[i] : F[i + 4];
            ull keep = hi ? F[i + 4] : F[i];
            F[i] = add2(keep, __shfl_xor_sync(0xffffffffu, give, 2));
        } }
    {   const bool hi = kc & 4;
        #pragma unroll
        for (int i = 0; i < 2; ++i) {
            ull give = hi ? F[i] : F[i + 2];
            ull keep = hi ? F[i + 2] : F[i];
            F[i] = add2(keep, __shfl_xor_sync(0xffffffffu, give, 4));
        } }
    {   const bool hi = kc & 8;
        ull give = hi ? F[0] : F[1];
        ull keep = hi ? F[1] : F[0];
        F[0] = add2(keep, __shfl_xor_sync(0xffffffffu, give, 8)); }
    const int rp = ((kc & 1) << 1) | ((kc >> 1) & 1);
    const int bb = (((kc >> 2) & 1) << 1) | ((kc >> 3) & 1);
    const int row0 = (rg << 3) + (rp << 1);
    float2 v = unpack2(F[0]);
    gates[row0 * GS + (bg << 2) + bb]       = v.x;
    gates[(row0 + 1) * GS + (bg << 2) + bb] = v.y;
}

// push one 32-col h slice to the 3 peer ranks (64 v4 per rank, 192 msgs).
__device__ __forceinline__ void push_slice(const float* __restrict__ Hb,
                                           const uint32_t* hrem, int irank,
                                           int stid, int buf, int rowbase)
{
    const int q  = stid >> 2;
    const int r4 = stid & 3;
    if (r4 != irank) {
        const int foff = buf + (rowbase + (q >> 1)) * HS + ((q & 1) << 2);
        float4 v = *reinterpret_cast<const float4*>(Hb + foff);
        stc_v4(hrem[r4] + ((uint32_t)foff << 2), v);
    }
}

__global__ void __launch_bounds__(SC_THREADS, 1) __cluster_dims__(CL_N, 1, 1)
scan_kernel(const float* __restrict__ w_hh0, const float* __restrict__ w_ih1,
            const float* __restrict__ w_hh1, const float* __restrict__ b_ih1,
            const float* __restrict__ b_hh1, const float* __restrict__ fc_w,
            const float* __restrict__ fc_b,  float* __restrict__ out)
{
    extern __shared__ float s2[];
    float* W0T  = s2 + W0T_OFF;
    float* W1T  = s2 + W1T_OFF;   // k 0..127 = w_ih1, 128..255 = w_hh1
    float* Hbuf = s2 + H_OFF;     // [buf][k 0..255][b] stride HS
    float* G0   = s2 + GT0_OFF;
    float* G1   = s2 + GT1_OFF;

    const int tid = threadIdx.x;
    uint32_t rank;
    asm("mov.u32 %0, %%cluster_ctarank;" : "=r"(rank));
    const int irank = (int)rank;
    const int cbase = (blockIdx.x >> 2) * BPC;

    // ---- prologue: rotated W slices ----
    for (int idx = tid; idx < 128 * 128; idx += SC_THREADS) {
        int rl = idx >> 7, k = idx & 127;
        int grow = ((rl >> 5) << 7) + irank * 32 + (rl & 31);
        int sa0 = (k << 7) + ((((rl >> 2) + k) & 31) << 2) + (rl & 3);
        int sa1 = ((128 + k) << 7) + ((((rl >> 2) + 128 + k) & 31) << 2) + (rl & 3);
        W0T[sa0] = w_hh0[grow * H_ + k];
        W1T[sa0] = w_ih1[grow * H_ + k];
        W1T[sa1] = w_hh1[grow * H_ + k];
    }
    for (int i = tid; i < 2 * 256 * HS; i += SC_THREADS) Hbuf[i] = 0.0f;

    const uint32_t hloc = smem_u32(Hbuf);
    uint32_t hrem[4];
    #pragma unroll
    for (int r = 0; r < 4; ++r) hrem[r] = mapa_u32(hloc, (uint32_t)r);

    // GEMM mapping
    const int kc = tid & 15;
    const int tl = tid >> 4;
    const int bg = tl & 1;
    const int rg = tl >> 1;        // rows 8rg..8rg+7
    // ew mapping: stid = (col,batch) pair; tid<256 -> layer 1, tid>=256 -> layer 0
    const int stid = tid & 255;
    const int eb  = stid >> 5;
    const int ej  = stid & 31;
    const int col = irank * 32 + ej;
    const float* xgbase = g_xg0 + (size_t)(cbase + eb) * G_ + col;

    // layer-1 biases live in tid<256; xg state lives in tid>=256
    float bi1i = 0.f, bi1f = 0.f, bi1g = 0.f, bi1o = 0.f;
    if (tid < 256) {
        bi1i = __ldg(b_ih1 + col)       + __ldg(b_hh1 + col);
        bi1f = __ldg(b_ih1 + 128 + col) + __ldg(b_hh1 + 128 + col);
        bi1g = __ldg(b_ih1 + 256 + col) + __ldg(b_hh1 + 256 + col);
        bi1o = __ldg(b_ih1 + 384 + col) + __ldg(b_hh1 + 384 + col);
    }

    CLUSTER_SYNC();   // zeros visible cluster-wide

    float c0 = 0.0f, c1 = 0.0f;
    float xg_i = 0.f, xg_f = 0.f, xg_g = 0.f, xg_o = 0.f;

    // ---- pre-loop: h0(0) computed by layer-0 threads (tid>=256) ----
    if (tid >= 256) {
        float i0 = __ldg(xgbase);
        float g0 = __ldg(xgbase + 256), o0 = __ldg(xgbase + 384);
        float iv = sigf(i0), gv = tanh_f(g0), ov = sigf(o0);
        c0 = iv * gv;
        Hbuf[col * HS + eb] = ov * tanh_f(c0);
        const float* xp = xgbase + (size_t)1 * (B_ * G_);
        xg_i = __ldg(xp); xg_f = __ldg(xp + 128);
        xg_g = __ldg(xp + 256); xg_o = __ldg(xp + 384);
    }
    __syncthreads();
    if (tid < 256) push_slice(Hbuf, hrem, irank, stid, 0, irank * 32);
    CLUSTER_SYNC();   // B(-1): h0(0) visible everywhere

    for (int t = 0; t < T_; ++t) {
        const int bufT = (t & 1) ? 3072 : 0;   // h0(t); receives h1(t)
        const int bufP = (t & 1) ? 0 : 3072;   // h1(t-1); receives h0(t+1)

        // ---- merged GEMM1a + GEMM0 (shared h0(t) loads), then GEMM1b ----
        ull acc1[16], acc0[16];
        #pragma unroll
        for (int i = 0; i < 16; ++i) { acc1[i] = 0ull; acc0[i] = 0ull; }
        gemm_dual(W1T, W0T, Hbuf + bufT, kc, rg, bg, acc1, acc0);
        gemm_half(W1T, Hbuf + bufP, kc, rg, bg, 128, acc1);
        fold_store(acc1, G1, kc, rg, bg);
        fold_store(acc0, G0, kc, rg, bg);

        __syncthreads();

        // ---- split elementwise: tid<256 layer 1, tid>=256 layer 0 ----
        if (tid < 256) {
            float a1i = G1[ej * GS + eb]        + bi1i;
            float a1f = G1[(32 + ej) * GS + eb] + bi1f;
            float a1g = G1[(64 + ej) * GS + eb] + bi1g;
            float a1o = G1[(96 + ej) * GS + eb] + bi1o;
            float iv1 = sigf(a1i), fv1 = sigf(a1f), gv1 = tanh_f(a1g), ov1 = sigf(a1o);
            c1 = fv1 * c1 + iv1 * gv1;
            Hbuf[bufT + (128 + col) * HS + eb] = ov1 * tanh_f(c1);
        } else {
            float a0i = G0[ej * GS + eb]        + xg_i;
            float a0f = G0[(32 + ej) * GS + eb] + xg_f;
            float a0g = G0[(64 + ej) * GS + eb] + xg_g;
            float a0o = G0[(96 + ej) * GS + eb] + xg_o;
            float iv0 = sigf(a0i), fv0 = sigf(a0f), gv0 = tanh_f(a0g), ov0 = sigf(a0o);
            c0 = fv0 * c0 + iv0 * gv0;
            Hbuf[bufP + col * HS + eb] = ov0 * tanh_f(c0);
        }
        __syncthreads();                        // local h visible to pushers

        // ---- push both slices concurrently ----
        if (tid < 256) push_slice(Hbuf, hrem, irank, stid, bufT, 128 + irank * 32);
        else           push_slice(Hbuf, hrem, irank, stid, bufP, irank * 32);
        CLUSTER_ARRIVE();                       // B(t) release

        // xg(t+2) prefetch (layer-0 threads) overlaps the barrier
        if (tid >= 256) {
            int tn = t + 2; if (tn > 511) tn = 511;
            const float* xp = xgbase + (size_t)tn * (B_ * G_);
            xg_i = __ldg(xp); xg_f = __ldg(xp + 128);
            xg_g = __ldg(xp + 256); xg_o = __ldg(xp + 384);
        }
        CLUSTER_WAIT();                         // h0(t+1), h1(t) visible
    }

    // ---- epilogue: h1(511) in buf1 (t=511 -> bufT=3072), rows 128..255 ----
    if (irank == 0 && tid < 256) {
        const int b = tid >> 5;
        const int l = tid & 31;
        float ssum = 0.0f;
        #pragma unroll
        for (int cc = 0; cc < 4; ++cc) {
            int c = l * 4 + cc;
            ssum += Hbuf[3072 + (128 + c) * HS + b] * __ldg(fc_w + c);
        }
        #pragma unroll
        for (int d = 16; d > 0; d >>= 1)
            ssum += __shfl_xor_sync(0xffffffffu, ssum, d);
        if (l == 0) out[cbase + b] = ssum + __ldg(fc_b);
    }
    CLUSTER_SYNC();
}

// ---------------------------------------------------------------------------
extern "C" void kernel_launch(void* const* d_in, const int* in_sizes, int n_in,
                              void* d_out, int out_size)
{
    const float* x     = (const float*)d_in[0];
    const float* w_ih0 = (const float*)d_in[1];
    const float* w_hh0 = (const float*)d_in[2];
    const float* b_ih0 = (const float*)d_in[3];
    const float* b_hh0 = (const float*)d_in[4];
    const float* w_ih1 = (const float*)d_in[5];
    const float* w_hh1 = (const float*)d_in[6];
    const float* b_ih1 = (const float*)d_in[7];
    const float* b_hh1 = (const float*)d_in[8];
    const float* fc_w  = (const float*)d_in[9];
    const float* fc_b  = (const float*)d_in[10];
    float* out = (float*)d_out;

    const int p1_smem = P1_SMEM_FLOATS * 4;
    const int sc_smem = SC_SMEM_FLOATS * 4;
    cudaFuncSetAttribute(p1_kernel,   cudaFuncAttributeMaxDynamicSharedMemorySize, p1_smem);
    cudaFuncSetAttribute(scan_kernel, cudaFuncAttributeMaxDynamicSharedMemorySize, sc_smem);

    pt_kernel<<<32, 1024>>>(w_ih0);
    p1_kernel<<<(B_ * T_) / P1_ROWS, P1_THREADS, p1_smem>>>(x, b_ih0, b_hh0);
    scan_kernel<<<(B_ / BPC) * CL_N, SC_THREADS, sc_smem>>>(
        w_hh0, w_ih1, w_hh1, b_ih1, b_hh1, fc_w, fc_b, out);
}